// round 3
// baseline (speedup 1.0000x reference)
#include <cuda_runtime.h>
#include <cuda_bf16.h>
#include <cstdint>

// ============================================================================
// LSTM decoder, B=2048, T=32, H=1024, inference path (pred feedback).
// sm_100 (no 'a' features): bf16 mma.sync GEMM + cp.async 3-stage pipeline.
//
// Per step: D[2048,4096] = A_ext[2048,3072] * W_ext[4096,3072]^T
//   A_ext = [h_hi | h_hi | h_lo], W_ext = [W_hi | W_lo | W_hi]  (bf16, K-major)
// W columns permuted so col n -> (unit n>>2, gate n&3), gate order i,f,g,o.
// One kernel launch per time step = grid-wide dependency barrier.
//
// R2 fix: h operand (g_Aext) is DOUBLE-BUFFERED. Step t reads buf[t&1] and
// writes buf[(t+1)&1]; previously epilogue writes raced with other CTAs'
// mainloop reads of the same rows (rel_err 0.25).
// ============================================================================

#define BATCH 2048
#define TT    32
#define HH    1024
#define N4    4096
#define KE    3072            // 3*H
#define TM    128             // M tile
#define TN    256             // N tile
#define KC    64              // K chunk (bf16) = 128 bytes
#define NCH   (KE / KC)       // 48
#define NTHREADS 512
#define STAGES 3
#define STAGE_BYTES 49152     // A 16KB + B 32KB
#define SMEM_BYTES  (1024 + STAGES * STAGE_BYTES)

// Scratch (device globals; no allocation allowed)
__device__ __align__(256) __nv_bfloat16 g_Wext[(size_t)N4 * KE];        // 24 MB
__device__ __align__(256) __nv_bfloat16 g_Aext[2][(size_t)BATCH * KE];  // 2 x 12 MB
__device__ __align__(256) float g_c[(size_t)BATCH * HH];                // 8 MB
__device__ __align__(256) float g_predsum[BATCH * TT];
__device__ __align__(256) float g_bias[N4];
__device__ __align__(256) float g_w0[N4];
__device__ __align__(256) float g_w1[N4];
__device__ __align__(256) float g_fcW[HH];

// ---------------------------------------------------------------------------
// helpers
// ---------------------------------------------------------------------------
__device__ __forceinline__ uint32_t smem_u32(const void* p) {
    uint32_t a;
    asm("{ .reg .u64 t; cvta.to.shared.u64 t, %1; cvt.u32.u64 %0, t; }" : "=r"(a) : "l"(p));
    return a;
}
__device__ __forceinline__ void cp_async16(uint32_t dst, const void* src) {
    asm volatile("cp.async.cg.shared.global [%0], [%1], 16;" :: "r"(dst), "l"(src) : "memory");
}
__device__ __forceinline__ void cp_commit() {
    asm volatile("cp.async.commit_group;" ::: "memory");
}
__device__ __forceinline__ uint32_t sw128(uint32_t off) {
    return off ^ ((off >> 3) & 0x70u);
}
__device__ __forceinline__ void ldsm_x4(uint32_t& r0, uint32_t& r1, uint32_t& r2, uint32_t& r3,
                                        uint32_t addr) {
    asm volatile("ldmatrix.sync.aligned.m8n8.x4.shared.b16 {%0,%1,%2,%3}, [%4];"
                 : "=r"(r0), "=r"(r1), "=r"(r2), "=r"(r3) : "r"(addr));
}
__device__ __forceinline__ void mma_bf16(float* d, const uint32_t* a, const uint32_t* b) {
    asm volatile(
        "mma.sync.aligned.m16n8k16.row.col.f32.bf16.bf16.f32 "
        "{%0,%1,%2,%3}, {%4,%5,%6,%7}, {%8,%9}, {%0,%1,%2,%3};"
        : "+f"(d[0]), "+f"(d[1]), "+f"(d[2]), "+f"(d[3])
        : "r"(a[0]), "r"(a[1]), "r"(a[2]), "r"(a[3]), "r"(b[0]), "r"(b[1]));
}
__device__ __forceinline__ float sigf(float x) {
    return __fdividef(1.0f, 1.0f + __expf(-x));
}
__device__ __forceinline__ float tanh_f(float x) {
    float xc = fminf(fmaxf(x, -15.0f), 15.0f);
    float e = __expf(2.0f * xc);
    return 1.0f - __fdividef(2.0f, e + 1.0f);
}

// ---------------------------------------------------------------------------
// Prep kernels
// ---------------------------------------------------------------------------
__global__ void prep_weights(const float* __restrict__ W_hh, const float* __restrict__ W_ih,
                             const float* __restrict__ b_ih, const float* __restrict__ b_hh,
                             const float* __restrict__ fc_W) {
    int idx = blockIdx.x * blockDim.x + threadIdx.x;   // 0 .. 4096*1024-1
    int n = idx >> 10, k = idx & 1023;
    int r = (n & 3) * HH + (n >> 2);                   // col n -> orig W_hh row
    float w = W_hh[(size_t)r * HH + k];
    __nv_bfloat16 hi = __float2bfloat16(w);
    __nv_bfloat16 lo = __float2bfloat16(w - __bfloat162float(hi));
    size_t base = (size_t)n * KE;
    g_Wext[base + k] = hi;
    g_Wext[base + HH + k] = lo;
    g_Wext[base + 2 * HH + k] = hi;
    if (idx < N4) {
        int rr = (idx & 3) * HH + (idx >> 2);
        g_bias[idx] = b_ih[rr] + b_hh[rr];
        g_w0[idx] = W_ih[rr * 2 + 0];
        g_w1[idx] = W_ih[rr * 2 + 1];
    }
    if (idx < HH) g_fcW[idx] = fc_W[idx];
}

__global__ void prep_state(const float* __restrict__ hidden, const float* __restrict__ cell) {
    int idx = blockIdx.x * blockDim.x + threadIdx.x;   // 0 .. 2048*1024-1
    g_c[idx] = cell[idx];
    float h = hidden[idx];
    __nv_bfloat16 hi = __float2bfloat16(h);
    __nv_bfloat16 lo = __float2bfloat16(h - __bfloat162float(hi));
    int b = idx >> 10, u = idx & 1023;
    size_t base = (size_t)b * KE;
    g_Aext[0][base + u] = hi;
    g_Aext[0][base + HH + u] = hi;
    g_Aext[0][base + 2 * HH + u] = lo;
    if (idx < BATCH * TT) g_predsum[idx] = 0.0f;
}

__global__ void finalize_out(float* __restrict__ out, const float* __restrict__ fc_b) {
    int idx = blockIdx.x * blockDim.x + threadIdx.x;
    if (idx < BATCH * TT) out[idx] = g_predsum[idx] + fc_b[0];
}

// ---------------------------------------------------------------------------
// Step kernel: GEMM (tile 128x256, K=3072) + fused LSTM cell epilogue
// 512 threads = 16 warps; warp tile 64x32: warp_m = wid&1, warp_n = wid>>1.
// ---------------------------------------------------------------------------
__global__ void __launch_bounds__(NTHREADS)
step_kernel(int t, const float* __restrict__ future_fd, const float* __restrict__ fc_b) {
    const __nv_bfloat16* __restrict__ Asrc = g_Aext[t & 1];
    __nv_bfloat16* __restrict__ Adst = g_Aext[(t + 1) & 1];

    extern __shared__ char smem_raw[];
    uint32_t sb = smem_u32(smem_raw);
    uint32_t ab = (sb + 1023u) & ~1023u;
    char* smem = smem_raw + (ab - sb);
    const uint32_t tiles = ab;

    const int tid = threadIdx.x;
    const int wid = tid >> 5;
    const int lid = tid & 31;
    const int wm = wid & 1;          // 0..1
    const int wn = wid >> 1;         // 0..7
    const int m0 = blockIdx.x * TM;
    const int n0 = blockIdx.y * TN;

    // ---- chunk loader: 384 rows x 128B (A rows 0..127, B rows 0..255) ------
    auto load_chunk = [&](int c, int s) {
        const int k0 = c * KC;
        const uint32_t base = tiles + s * STAGE_BYTES;
        #pragma unroll
        for (int j = 0; j < 6; j++) {
            int li = tid + j * NTHREADS;
            int ri = li >> 3, q = li & 7;
            if (ri < TM) {
                uint32_t dst = base + sw128((uint32_t)(ri * 128 + q * 16));
                cp_async16(dst, Asrc + ((size_t)(m0 + ri) * KE + k0 + q * 8));
            } else {
                int rb = ri - TM;
                uint32_t dst = base + 16384 + sw128((uint32_t)(rb * 128 + q * 16));
                cp_async16(dst, g_Wext + ((size_t)(n0 + rb) * KE + k0 + q * 8));
            }
        }
        cp_commit();
    };

    // ---- lane constants for ldmatrix addressing ----------------------------
    const int a_lr = lid & 15;                     // A row within 16
    const int a_ch = (lid >> 4) << 4;              // A k-byte offset (0/16)
    const int b_nr = (lid & 7) + ((lid >> 4) << 3);// B n-row within 16
    const int b_ch = ((lid >> 3) & 1) << 4;        // B k-byte offset (0/16)

    float acc[4][4][4];
    #pragma unroll
    for (int i = 0; i < 4; i++)
        #pragma unroll
        for (int j = 0; j < 4; j++)
            #pragma unroll
            for (int r = 0; r < 4; r++) acc[i][j][r] = 0.0f;

    load_chunk(0, 0);
    load_chunk(1, 1);

    #pragma unroll 1
    for (int c = 0; c < NCH; c++) {
        if (c < NCH - 2) asm volatile("cp.async.wait_group 1;" ::: "memory");
        else             asm volatile("cp.async.wait_group 0;" ::: "memory");
        __syncthreads();

        if (c + 2 < NCH) load_chunk(c + 2, (c + 2) % STAGES);

        const uint32_t As = tiles + (c % STAGES) * STAGE_BYTES;
        const uint32_t Bs = As + 16384;

        #pragma unroll
        for (int ks = 0; ks < 4; ks++) {
            uint32_t a[4][4], b[4][2];
            #pragma unroll
            for (int mi = 0; mi < 4; mi++) {
                uint32_t off = (uint32_t)((wm * 64 + mi * 16 + a_lr) * 128 + ks * 32 + a_ch);
                ldsm_x4(a[mi][0], a[mi][1], a[mi][2], a[mi][3], As + sw128(off));
            }
            #pragma unroll
            for (int nb = 0; nb < 2; nb++) {
                uint32_t off = (uint32_t)((wn * 32 + nb * 16 + b_nr) * 128 + ks * 32 + b_ch);
                ldsm_x4(b[nb * 2][0], b[nb * 2][1], b[nb * 2 + 1][0], b[nb * 2 + 1][1],
                        Bs + sw128(off));
            }
            #pragma unroll
            for (int mi = 0; mi < 4; mi++)
                #pragma unroll
                for (int j = 0; j < 4; j++)
                    mma_bf16(acc[mi][j], a[mi], b[j]);
        }
    }
    __syncthreads();   // smem stages now reusable as epilogue scratch

    // ---- epilogue: gates -> smem (two 128-col halves), fused cell update ---
    float* gates = (float*)smem;                  // 128 rows x 132 floats pitch
    const int g = lid >> 2, tg = lid & 3;
    const float fcb = fc_b[0];

    #pragma unroll 1
    for (int half = 0; half < 2; half++) {
        if ((wn >> 2) == half) {
            const int clb = (wn & 3) * 32;
            #pragma unroll
            for (int mi = 0; mi < 4; mi++) {
                const int r = wm * 64 + mi * 16 + g;
                #pragma unroll
                for (int j = 0; j < 4; j++) {
                    const int cl = clb + j * 8 + 2 * tg;
                    *(float2*)&gates[r * 132 + cl]       = make_float2(acc[mi][j][0], acc[mi][j][1]);
                    *(float2*)&gates[(r + 8) * 132 + cl] = make_float2(acc[mi][j][2], acc[mi][j][3]);
                }
            }
        }
        __syncthreads();

        #pragma unroll 1
        for (int jj = 0; jj < 8; jj++) {
            const int idx = tid + jj * NTHREADS;       // 4096 = 128 rows x 32 units
            const int row = idx >> 5, u = idx & 31;
            const int n = n0 + half * 128 + 4 * u;
            const int ug = n >> 2;                     // global unit 0..1023
            const int b = m0 + row;

            float4 gv = *(float4*)&gates[row * 132 + 4 * u];
            float4 bs = ((const float4*)g_bias)[n >> 2];
            float4 w0 = ((const float4*)g_w0)[n >> 2];
            float4 w1 = ((const float4*)g_w1)[n >> 2];

            float prev = 0.0f;
            if (t > 0) prev = g_predsum[b * TT + (t - 1)] + fcb;
            const float fdv = future_fd[b * TT + t];

            float gi = gv.x + bs.x + prev * w0.x + fdv * w1.x;
            float gf = gv.y + bs.y + prev * w0.y + fdv * w1.y;
            float gg = gv.z + bs.z + prev * w0.z + fdv * w1.z;
            float go = gv.w + bs.w + prev * w0.w + fdv * w1.w;

            float co = g_c[(size_t)b * HH + ug];
            float cn = sigf(gf) * co + sigf(gi) * tanh_f(gg);
            float h  = sigf(go) * tanh_f(cn);
            g_c[(size_t)b * HH + ug] = cn;

            __nv_bfloat16 hi = __float2bfloat16(h);
            __nv_bfloat16 lo = __float2bfloat16(h - __bfloat162float(hi));
            size_t abse = (size_t)b * KE;
            Adst[abse + ug] = hi;
            Adst[abse + HH + ug] = hi;
            Adst[abse + 2 * HH + ug] = lo;

            float fcp = h * g_fcW[ug];
            #pragma unroll
            for (int o = 16; o; o >>= 1) fcp += __shfl_down_sync(0xFFFFFFFFu, fcp, o);
            if (lid == 0) atomicAdd(&g_predsum[b * TT + t], fcp);
        }
        __syncthreads();
    }
}

// ---------------------------------------------------------------------------
// Host launcher
// ---------------------------------------------------------------------------
extern "C" void kernel_launch(void* const* d_in, const int* in_sizes, int n_in,
                              void* d_out, int out_size) {
    const float* future_fd = (const float*)d_in[0];
    const float* hidden    = (const float*)d_in[1];
    const float* cell      = (const float*)d_in[2];
    const float* W_ih      = (const float*)d_in[3];
    const float* W_hh      = (const float*)d_in[4];
    const float* b_ih      = (const float*)d_in[5];
    const float* b_hh      = (const float*)d_in[6];
    const float* fc_W      = (const float*)d_in[7];
    const float* fc_b      = (const float*)d_in[8];

    cudaFuncSetAttribute(step_kernel, cudaFuncAttributeMaxDynamicSharedMemorySize, SMEM_BYTES);

    prep_weights<<<(N4 * HH) / 256, 256>>>(W_hh, W_ih, b_ih, b_hh, fc_W);
    prep_state<<<(BATCH * HH) / 256, 256>>>(hidden, cell);
    for (int t = 0; t < TT; t++) {
        step_kernel<<<dim3(BATCH / TM, N4 / TN), NTHREADS, SMEM_BYTES>>>(t, future_fd, fc_b);
    }
    finalize_out<<<(BATCH * TT + 255) / 256, 256>>>((float*)d_out, fc_b);
}

// round 4
// speedup vs baseline: 1.5846x; 1.5846x over previous
#include <cuda_runtime.h>
#include <cuda_fp16.h>
#include <cuda_bf16.h>
#include <cstdint>

// ============================================================================
// LSTM decoder, B=2048, T=32, H=1024, inference path (pred feedback).
// sm_100: fp16 mma.sync GEMM + cp.async 3-stage pipeline, 2 CTAs/SM.
//
// Per step: D[2048,4096] = A_ext[2048,2048] * W_ext[4096,2048]^T
//   A_ext = [h_hi | h_lo] (fp16, exact h),  W_ext = [W_hi | W_hi]
//   => gate = h * fp16(W); error ~ eps_fp16/2 ~ 1e-4 rel (measured compounding ~1).
// W columns permuted so col n -> (unit n>>2, gate n&3), gate order i,f,g,o.
// One kernel launch per time step = grid-wide dependency barrier.
// h operand double-buffered across steps (R2 race fix).
// ============================================================================

#define BATCH 2048
#define TT    32
#define HH    1024
#define N4    4096
#define KE    2048            // 2*H
#define TM    128             // M tile
#define TN    128             // N tile
#define KC    64              // K chunk (fp16) = 128 bytes
#define NCH   (KE / KC)       // 32
#define NTHREADS 256
#define STAGES 3
#define STAGE_BYTES 32768     // A 16KB + B 16KB
#define SMEM_BYTES  (1024 + STAGES * STAGE_BYTES)

// Scratch (device globals; no allocation allowed)
__device__ __align__(256) __half g_Wext[(size_t)N4 * KE];        // 16 MB
__device__ __align__(256) __half g_Aext[2][(size_t)BATCH * KE];  // 2 x 8 MB
__device__ __align__(256) float g_c[(size_t)BATCH * HH];         // 8 MB
__device__ __align__(256) float g_predsum[BATCH * TT];
__device__ __align__(256) float g_bias[N4];
__device__ __align__(256) float g_w0[N4];
__device__ __align__(256) float g_w1[N4];
__device__ __align__(256) float g_fcW[HH];

// ---------------------------------------------------------------------------
// helpers
// ---------------------------------------------------------------------------
__device__ __forceinline__ uint32_t smem_u32(const void* p) {
    uint32_t a;
    asm("{ .reg .u64 t; cvta.to.shared.u64 t, %1; cvt.u32.u64 %0, t; }" : "=r"(a) : "l"(p));
    return a;
}
__device__ __forceinline__ void cp_async16(uint32_t dst, const void* src) {
    asm volatile("cp.async.cg.shared.global [%0], [%1], 16;" :: "r"(dst), "l"(src) : "memory");
}
__device__ __forceinline__ void cp_commit() {
    asm volatile("cp.async.commit_group;" ::: "memory");
}
__device__ __forceinline__ uint32_t sw128(uint32_t off) {
    return off ^ ((off >> 3) & 0x70u);
}
__device__ __forceinline__ void ldsm_x4(uint32_t& r0, uint32_t& r1, uint32_t& r2, uint32_t& r3,
                                        uint32_t addr) {
    asm volatile("ldmatrix.sync.aligned.m8n8.x4.shared.b16 {%0,%1,%2,%3}, [%4];"
                 : "=r"(r0), "=r"(r1), "=r"(r2), "=r"(r3) : "r"(addr));
}
__device__ __forceinline__ void mma_fp16(float* d, const uint32_t* a, const uint32_t* b) {
    asm volatile(
        "mma.sync.aligned.m16n8k16.row.col.f32.f16.f16.f32 "
        "{%0,%1,%2,%3}, {%4,%5,%6,%7}, {%8,%9}, {%0,%1,%2,%3};"
        : "+f"(d[0]), "+f"(d[1]), "+f"(d[2]), "+f"(d[3])
        : "r"(a[0]), "r"(a[1]), "r"(a[2]), "r"(a[3]), "r"(b[0]), "r"(b[1]));
}
__device__ __forceinline__ float sigf(float x) {
    return __fdividef(1.0f, 1.0f + __expf(-x));
}
__device__ __forceinline__ float tanh_f(float x) {
    float xc = fminf(fmaxf(x, -15.0f), 15.0f);
    float e = __expf(2.0f * xc);
    return 1.0f - __fdividef(2.0f, e + 1.0f);
}

// ---------------------------------------------------------------------------
// Prep kernels
// ---------------------------------------------------------------------------
__global__ void prep_weights(const float* __restrict__ W_hh, const float* __restrict__ W_ih,
                             const float* __restrict__ b_ih, const float* __restrict__ b_hh,
                             const float* __restrict__ fc_W) {
    int idx = blockIdx.x * blockDim.x + threadIdx.x;   // 0 .. 4096*1024-1
    int n = idx >> 10, k = idx & 1023;
    int r = (n & 3) * HH + (n >> 2);                   // col n -> orig W_hh row
    float w = W_hh[(size_t)r * HH + k];
    __half hi = __float2half(w);
    size_t base = (size_t)n * KE;
    g_Wext[base + k] = hi;
    g_Wext[base + HH + k] = hi;
    if (idx < N4) {
        int rr = (idx & 3) * HH + (idx >> 2);
        g_bias[idx] = b_ih[rr] + b_hh[rr];
        g_w0[idx] = W_ih[rr * 2 + 0];
        g_w1[idx] = W_ih[rr * 2 + 1];
    }
    if (idx < HH) g_fcW[idx] = fc_W[idx];
}

__global__ void prep_state(const float* __restrict__ hidden, const float* __restrict__ cell) {
    int idx = blockIdx.x * blockDim.x + threadIdx.x;   // 0 .. 2048*1024-1
    g_c[idx] = cell[idx];
    float h = hidden[idx];
    __half hi = __float2half(h);
    __half lo = __float2half(h - __half2float(hi));
    int b = idx >> 10, u = idx & 1023;
    size_t base = (size_t)b * KE;
    g_Aext[0][base + u] = hi;
    g_Aext[0][base + HH + u] = lo;
    if (idx < BATCH * TT) g_predsum[idx] = 0.0f;
}

__global__ void finalize_out(float* __restrict__ out, const float* __restrict__ fc_b) {
    int idx = blockIdx.x * blockDim.x + threadIdx.x;
    if (idx < BATCH * TT) out[idx] = g_predsum[idx] + fc_b[0];
}

// ---------------------------------------------------------------------------
// Step kernel: GEMM (tile 128x128, K=2048) + fused LSTM cell epilogue
// 256 threads = 8 warps; warp tile 64x32: warp_m = wid&1, warp_n = wid>>1.
// 2 CTAs/SM (launch_bounds) so barrier/load phases of one CTA overlap the
// other CTA's HMMA issue.
// ---------------------------------------------------------------------------
__global__ void __launch_bounds__(NTHREADS, 2)
step_kernel(int t, const float* __restrict__ future_fd, const float* __restrict__ fc_b) {
    const __half* __restrict__ Asrc = g_Aext[t & 1];
    __half* __restrict__ Adst = g_Aext[(t + 1) & 1];

    extern __shared__ char smem_raw[];
    uint32_t sb = smem_u32(smem_raw);
    uint32_t ab = (sb + 1023u) & ~1023u;
    char* smem = smem_raw + (ab - sb);
    const uint32_t tiles = ab;

    const int tid = threadIdx.x;
    const int wid = tid >> 5;
    const int lid = tid & 31;
    const int wm = wid & 1;          // 0..1  (64-row block)
    const int wn = wid >> 1;         // 0..3  (32-col block)
    const int m0 = blockIdx.x * TM;
    const int n0 = blockIdx.y * TN;

    // ---- chunk loader: 256 rows x 128B (A rows 0..127, B rows 0..127) ------
    auto load_chunk = [&](int c, int s) {
        const int k0 = c * KC;
        const uint32_t base = tiles + s * STAGE_BYTES;
        #pragma unroll
        for (int j = 0; j < 8; j++) {
            int li = tid + j * NTHREADS;
            int ri = li >> 3, q = li & 7;
            if (ri < TM) {
                uint32_t dst = base + sw128((uint32_t)(ri * 128 + q * 16));
                cp_async16(dst, Asrc + ((size_t)(m0 + ri) * KE + k0 + q * 8));
            } else {
                int rb = ri - TM;
                uint32_t dst = base + 16384 + sw128((uint32_t)(rb * 128 + q * 16));
                cp_async16(dst, g_Wext + ((size_t)(n0 + rb) * KE + k0 + q * 8));
            }
        }
        cp_commit();
    };

    // ---- lane constants for ldmatrix addressing ----------------------------
    const int a_lr = lid & 15;                      // A row within 16
    const int a_ch = (lid >> 4) << 4;               // A k-byte offset (0/16)
    const int b_nr = (lid & 7) + ((lid >> 4) << 3); // B n-row within 16
    const int b_ch = ((lid >> 3) & 1) << 4;         // B k-byte offset (0/16)

    float acc[4][4][4];
    #pragma unroll
    for (int i = 0; i < 4; i++)
        #pragma unroll
        for (int j = 0; j < 4; j++)
            #pragma unroll
            for (int r = 0; r < 4; r++) acc[i][j][r] = 0.0f;

    load_chunk(0, 0);
    load_chunk(1, 1);

    #pragma unroll 1
    for (int c = 0; c < NCH; c++) {
        if (c < NCH - 2) asm volatile("cp.async.wait_group 1;" ::: "memory");
        else             asm volatile("cp.async.wait_group 0;" ::: "memory");
        __syncthreads();

        if (c + 2 < NCH) load_chunk(c + 2, (c + 2) % STAGES);

        const uint32_t As = tiles + (c % STAGES) * STAGE_BYTES;
        const uint32_t Bs = As + 16384;

        #pragma unroll
        for (int ks = 0; ks < 4; ks++) {
            uint32_t a[4][4], b[4][2];
            #pragma unroll
            for (int mi = 0; mi < 4; mi++) {
                uint32_t off = (uint32_t)((wm * 64 + mi * 16 + a_lr) * 128 + ks * 32 + a_ch);
                ldsm_x4(a[mi][0], a[mi][1], a[mi][2], a[mi][3], As + sw128(off));
            }
            #pragma unroll
            for (int nb = 0; nb < 2; nb++) {
                uint32_t off = (uint32_t)((wn * 32 + nb * 16 + b_nr) * 128 + ks * 32 + b_ch);
                ldsm_x4(b[nb * 2][0], b[nb * 2][1], b[nb * 2 + 1][0], b[nb * 2 + 1][1],
                        Bs + sw128(off));
            }
            #pragma unroll
            for (int mi = 0; mi < 4; mi++)
                #pragma unroll
                for (int j = 0; j < 4; j++)
                    mma_fp16(acc[mi][j], a[mi], b[j]);
        }
    }
    __syncthreads();   // smem stages now reusable as epilogue scratch

    // ---- epilogue: gates -> smem, fused cell update ------------------------
    float* gates = (float*)smem;                  // 128 rows x 132 floats pitch
    const int g = lid >> 2, tg = lid & 3;
    const float fcb = fc_b[0];

    {
        const int clb = wn * 32;
        #pragma unroll
        for (int mi = 0; mi < 4; mi++) {
            const int r = wm * 64 + mi * 16 + g;
            #pragma unroll
            for (int j = 0; j < 4; j++) {
                const int cl = clb + j * 8 + 2 * tg;
                *(float2*)&gates[r * 132 + cl]       = make_float2(acc[mi][j][0], acc[mi][j][1]);
                *(float2*)&gates[(r + 8) * 132 + cl] = make_float2(acc[mi][j][2], acc[mi][j][3]);
            }
        }
    }
    __syncthreads();

    #pragma unroll 1
    for (int jj = 0; jj < 16; jj++) {
        const int idx = tid + jj * NTHREADS;       // 4096 = 128 rows x 32 units
        const int row = idx >> 5, u = idx & 31;
        const int n = n0 + 4 * u;
        const int ug = n >> 2;                     // global unit 0..1023
        const int b = m0 + row;

        float4 gv = *(float4*)&gates[row * 132 + 4 * u];
        float4 bs = ((const float4*)g_bias)[n >> 2];
        float4 w0 = ((const float4*)g_w0)[n >> 2];
        float4 w1 = ((const float4*)g_w1)[n >> 2];

        float prev = 0.0f;
        if (t > 0) prev = g_predsum[b * TT + (t - 1)] + fcb;
        const float fdv = future_fd[b * TT + t];

        float gi = gv.x + bs.x + prev * w0.x + fdv * w1.x;
        float gf = gv.y + bs.y + prev * w0.y + fdv * w1.y;
        float gg = gv.z + bs.z + prev * w0.z + fdv * w1.z;
        float go = gv.w + bs.w + prev * w0.w + fdv * w1.w;

        float co = g_c[(size_t)b * HH + ug];
        float cn = sigf(gf) * co + sigf(gi) * tanh_f(gg);
        float h  = sigf(go) * tanh_f(cn);
        g_c[(size_t)b * HH + ug] = cn;

        __half hi = __float2half(h);
        __half lo = __float2half(h - __half2float(hi));
        size_t abse = (size_t)b * KE;
        Adst[abse + ug] = hi;
        Adst[abse + HH + ug] = lo;

        float fcp = h * g_fcW[ug];
        #pragma unroll
        for (int o = 16; o; o >>= 1) fcp += __shfl_down_sync(0xFFFFFFFFu, fcp, o);
        if (lid == 0) atomicAdd(&g_predsum[b * TT + t], fcp);
    }
}

// ---------------------------------------------------------------------------
// Host launcher
// ---------------------------------------------------------------------------
extern "C" void kernel_launch(void* const* d_in, const int* in_sizes, int n_in,
                              void* d_out, int out_size) {
    const float* future_fd = (const float*)d_in[0];
    const float* hidden    = (const float*)d_in[1];
    const float* cell      = (const float*)d_in[2];
    const float* W_ih      = (const float*)d_in[3];
    const float* W_hh      = (const float*)d_in[4];
    const float* b_ih      = (const float*)d_in[5];
    const float* b_hh      = (const float*)d_in[6];
    const float* fc_W      = (const float*)d_in[7];
    const float* fc_b      = (const float*)d_in[8];

    cudaFuncSetAttribute(step_kernel, cudaFuncAttributeMaxDynamicSharedMemorySize, SMEM_BYTES);

    prep_weights<<<(N4 * HH) / 256, 256>>>(W_hh, W_ih, b_ih, b_hh, fc_W);
    prep_state<<<(BATCH * HH) / 256, 256>>>(hidden, cell);
    for (int t = 0; t < TT; t++) {
        step_kernel<<<dim3(BATCH / TM, N4 / TN), NTHREADS, SMEM_BYTES>>>(t, future_fd, fc_b);
    }
    finalize_out<<<(BATCH * TT + 255) / 256, 256>>>((float*)d_out, fc_b);
}

// round 5
// speedup vs baseline: 2.6204x; 1.6537x over previous
#include <cuda_runtime.h>
#include <cuda_fp16.h>
#include <cstdint>

// ============================================================================
// LSTM decoder, B=2048, T=32, H=1024, inference path (pred feedback).
// sm_100: fp16 mma.sync GEMM + cp.async 3-stage pipeline, 2 CTAs/SM.
//
// Per step: D[2048,4096] = A[2048,1024](fp16 h) * W[4096,1024]^T (fp16)
// Single-term fp16: error = h-rounding + W-rounding, each ~1e-4 final
// (calibrated R3/R4: compounding factor ~1). Margin ~4x under 1e-3.
// W columns permuted so col n -> (unit n>>2, gate n&3), gate order i,f,g,o.
// One kernel launch per time step = grid-wide dependency barrier.
// h operand double-buffered across steps (R2 race fix).
// ============================================================================

#define BATCH 2048
#define TT    32
#define HH    1024
#define N4    4096
#define KE    1024            // K = H (single fp16 term)
#define TM    128             // M tile
#define TN    128             // N tile
#define KC    64              // K chunk (fp16) = 128 bytes
#define NCH   (KE / KC)       // 16
#define NTHREADS 256
#define STAGES 3
#define STAGE_BYTES 32768     // A 16KB + B 16KB
#define SMEM_BYTES  (1024 + STAGES * STAGE_BYTES)

// Scratch (device globals; no allocation allowed)
__device__ __align__(256) __half g_Wext[(size_t)N4 * KE];        // 8 MB
__device__ __align__(256) __half g_Aext[2][(size_t)BATCH * KE];  // 2 x 4 MB
__device__ __align__(256) float g_c[(size_t)BATCH * HH];         // 8 MB
__device__ __align__(256) float g_predsum[BATCH * TT];
__device__ __align__(256) float g_bias[N4];
__device__ __align__(256) float g_w0[N4];
__device__ __align__(256) float g_w1[N4];
__device__ __align__(256) float g_fcW[HH];

// ---------------------------------------------------------------------------
// helpers
// ---------------------------------------------------------------------------
__device__ __forceinline__ uint32_t smem_u32(const void* p) {
    uint32_t a;
    asm("{ .reg .u64 t; cvta.to.shared.u64 t, %1; cvt.u32.u64 %0, t; }" : "=r"(a) : "l"(p));
    return a;
}
__device__ __forceinline__ void cp_async16(uint32_t dst, const void* src) {
    asm volatile("cp.async.cg.shared.global [%0], [%1], 16;" :: "r"(dst), "l"(src) : "memory");
}
__device__ __forceinline__ void cp_commit() {
    asm volatile("cp.async.commit_group;" ::: "memory");
}
__device__ __forceinline__ uint32_t sw128(uint32_t off) {
    return off ^ ((off >> 3) & 0x70u);
}
__device__ __forceinline__ void ldsm_x4(uint32_t& r0, uint32_t& r1, uint32_t& r2, uint32_t& r3,
                                        uint32_t addr) {
    asm volatile("ldmatrix.sync.aligned.m8n8.x4.shared.b16 {%0,%1,%2,%3}, [%4];"
                 : "=r"(r0), "=r"(r1), "=r"(r2), "=r"(r3) : "r"(addr));
}
__device__ __forceinline__ void mma_fp16(float* d, const uint32_t* a, const uint32_t* b) {
    asm volatile(
        "mma.sync.aligned.m16n8k16.row.col.f32.f16.f16.f32 "
        "{%0,%1,%2,%3}, {%4,%5,%6,%7}, {%8,%9}, {%0,%1,%2,%3};"
        : "+f"(d[0]), "+f"(d[1]), "+f"(d[2]), "+f"(d[3])
        : "r"(a[0]), "r"(a[1]), "r"(a[2]), "r"(a[3]), "r"(b[0]), "r"(b[1]));
}
__device__ __forceinline__ float sigf(float x) {
    return __fdividef(1.0f, 1.0f + __expf(-x));
}
__device__ __forceinline__ float tanh_f(float x) {
    float xc = fminf(fmaxf(x, -15.0f), 15.0f);
    float e = __expf(2.0f * xc);
    return 1.0f - __fdividef(2.0f, e + 1.0f);
}

// ---------------------------------------------------------------------------
// Prep kernels
// ---------------------------------------------------------------------------
__global__ void prep_weights(const float* __restrict__ W_hh, const float* __restrict__ W_ih,
                             const float* __restrict__ b_ih, const float* __restrict__ b_hh,
                             const float* __restrict__ fc_W) {
    int idx = blockIdx.x * blockDim.x + threadIdx.x;   // 0 .. 4096*1024-1
    int n = idx >> 10, k = idx & 1023;
    int r = (n & 3) * HH + (n >> 2);                   // col n -> orig W_hh row
    g_Wext[(size_t)n * KE + k] = __float2half(W_hh[(size_t)r * HH + k]);
    if (idx < N4) {
        int rr = (idx & 3) * HH + (idx >> 2);
        g_bias[idx] = b_ih[rr] + b_hh[rr];
        g_w0[idx] = W_ih[rr * 2 + 0];
        g_w1[idx] = W_ih[rr * 2 + 1];
    }
    if (idx < HH) g_fcW[idx] = fc_W[idx];
}

__global__ void prep_state(const float* __restrict__ hidden, const float* __restrict__ cell) {
    int idx = blockIdx.x * blockDim.x + threadIdx.x;   // 0 .. 2048*1024-1
    g_c[idx] = cell[idx];
    g_Aext[0][idx] = __float2half(hidden[idx]);
    if (idx < BATCH * TT) g_predsum[idx] = 0.0f;
}

__global__ void finalize_out(float* __restrict__ out, const float* __restrict__ fc_b) {
    int idx = blockIdx.x * blockDim.x + threadIdx.x;
    if (idx < BATCH * TT) out[idx] = g_predsum[idx] + fc_b[0];
}

// ---------------------------------------------------------------------------
// Step kernel: GEMM (tile 128x128, K=1024) + fused LSTM cell epilogue
// 256 threads = 8 warps; warp tile 64x32: warp_m = wid&1, warp_n = wid>>1.
// 2 CTAs/SM so barrier/load phases of one CTA overlap the other's HMMA issue.
// ---------------------------------------------------------------------------
__global__ void __launch_bounds__(NTHREADS, 2)
step_kernel(int t, const float* __restrict__ future_fd, const float* __restrict__ fc_b) {
    const __half* __restrict__ Asrc = g_Aext[t & 1];
    __half* __restrict__ Adst = g_Aext[(t + 1) & 1];

    extern __shared__ char smem_raw[];
    uint32_t sb = smem_u32(smem_raw);
    uint32_t ab = (sb + 1023u) & ~1023u;
    char* smem = smem_raw + (ab - sb);
    const uint32_t tiles = ab;

    const int tid = threadIdx.x;
    const int wid = tid >> 5;
    const int lid = tid & 31;
    const int wm = wid & 1;          // 0..1  (64-row block)
    const int wn = wid >> 1;         // 0..3  (32-col block)
    const int m0 = blockIdx.x * TM;
    const int n0 = blockIdx.y * TN;

    // ---- chunk loader: 256 rows x 128B (A rows 0..127, B rows 0..127) ------
    auto load_chunk = [&](int c, int s) {
        const int k0 = c * KC;
        const uint32_t base = tiles + s * STAGE_BYTES;
        #pragma unroll
        for (int j = 0; j < 8; j++) {
            int li = tid + j * NTHREADS;
            int ri = li >> 3, q = li & 7;
            if (ri < TM) {
                uint32_t dst = base + sw128((uint32_t)(ri * 128 + q * 16));
                cp_async16(dst, Asrc + ((size_t)(m0 + ri) * KE + k0 + q * 8));
            } else {
                int rb = ri - TM;
                uint32_t dst = base + 16384 + sw128((uint32_t)(rb * 128 + q * 16));
                cp_async16(dst, g_Wext + ((size_t)(n0 + rb) * KE + k0 + q * 8));
            }
        }
        cp_commit();
    };

    // ---- lane constants for ldmatrix addressing ----------------------------
    const int a_lr = lid & 15;                      // A row within 16
    const int a_ch = (lid >> 4) << 4;               // A k-byte offset (0/16)
    const int b_nr = (lid & 7) + ((lid >> 4) << 3); // B n-row within 16
    const int b_ch = ((lid >> 3) & 1) << 4;         // B k-byte offset (0/16)

    float acc[4][4][4];
    #pragma unroll
    for (int i = 0; i < 4; i++)
        #pragma unroll
        for (int j = 0; j < 4; j++)
            #pragma unroll
            for (int r = 0; r < 4; r++) acc[i][j][r] = 0.0f;

    load_chunk(0, 0);
    load_chunk(1, 1);

    #pragma unroll 1
    for (int c = 0; c < NCH; c++) {
        if (c < NCH - 2) asm volatile("cp.async.wait_group 1;" ::: "memory");
        else             asm volatile("cp.async.wait_group 0;" ::: "memory");
        __syncthreads();

        if (c + 2 < NCH) load_chunk(c + 2, (c + 2) % STAGES);

        const uint32_t As = tiles + (c % STAGES) * STAGE_BYTES;
        const uint32_t Bs = As + 16384;

        #pragma unroll
        for (int ks = 0; ks < 4; ks++) {
            uint32_t a[4][4], b[4][2];
            #pragma unroll
            for (int mi = 0; mi < 4; mi++) {
                uint32_t off = (uint32_t)((wm * 64 + mi * 16 + a_lr) * 128 + ks * 32 + a_ch);
                ldsm_x4(a[mi][0], a[mi][1], a[mi][2], a[mi][3], As + sw128(off));
            }
            #pragma unroll
            for (int nb = 0; nb < 2; nb++) {
                uint32_t off = (uint32_t)((wn * 32 + nb * 16 + b_nr) * 128 + ks * 32 + b_ch);
                ldsm_x4(b[nb * 2][0], b[nb * 2][1], b[nb * 2 + 1][0], b[nb * 2 + 1][1],
                        Bs + sw128(off));
            }
            #pragma unroll
            for (int mi = 0; mi < 4; mi++)
                #pragma unroll
                for (int j = 0; j < 4; j++)
                    mma_fp16(acc[mi][j], a[mi], b[j]);
        }
    }
    __syncthreads();   // smem stages now reusable as epilogue scratch

    // ---- epilogue: gates -> smem, fused cell update ------------------------
    float* gates = (float*)smem;                  // 128 rows x 132 floats pitch
    const int g = lid >> 2, tg = lid & 3;
    const float fcb = fc_b[0];

    {
        const int clb = wn * 32;
        #pragma unroll
        for (int mi = 0; mi < 4; mi++) {
            const int r = wm * 64 + mi * 16 + g;
            #pragma unroll
            for (int j = 0; j < 4; j++) {
                const int cl = clb + j * 8 + 2 * tg;
                *(float2*)&gates[r * 132 + cl]       = make_float2(acc[mi][j][0], acc[mi][j][1]);
                *(float2*)&gates[(r + 8) * 132 + cl] = make_float2(acc[mi][j][2], acc[mi][j][3]);
            }
        }
    }
    __syncthreads();

    #pragma unroll 1
    for (int jj = 0; jj < 16; jj++) {
        const int idx = tid + jj * NTHREADS;       // 4096 = 128 rows x 32 units
        const int row = idx >> 5, u = idx & 31;
        const int n = n0 + 4 * u;
        const int ug = n >> 2;                     // global unit 0..1023
        const int b = m0 + row;

        float4 gv = *(float4*)&gates[row * 132 + 4 * u];
        float4 bs = ((const float4*)g_bias)[n >> 2];
        float4 w0 = ((const float4*)g_w0)[n >> 2];
        float4 w1 = ((const float4*)g_w1)[n >> 2];

        float prev = 0.0f;
        if (t > 0) prev = g_predsum[b * TT + (t - 1)] + fcb;
        const float fdv = future_fd[b * TT + t];

        float gi = gv.x + bs.x + prev * w0.x + fdv * w1.x;
        float gf = gv.y + bs.y + prev * w0.y + fdv * w1.y;
        float gg = gv.z + bs.z + prev * w0.z + fdv * w1.z;
        float go = gv.w + bs.w + prev * w0.w + fdv * w1.w;

        float co = g_c[(size_t)b * HH + ug];
        float cn = sigf(gf) * co + sigf(gi) * tanh_f(gg);
        float h  = sigf(go) * tanh_f(cn);
        g_c[(size_t)b * HH + ug] = cn;

        Adst[(size_t)b * KE + ug] = __float2half(h);

        float fcp = h * g_fcW[ug];
        #pragma unroll
        for (int o = 16; o; o >>= 1) fcp += __shfl_down_sync(0xFFFFFFFFu, fcp, o);
        if (lid == 0) atomicAdd(&g_predsum[b * TT + t], fcp);
    }
}

// ---------------------------------------------------------------------------
// Host launcher
// ---------------------------------------------------------------------------
extern "C" void kernel_launch(void* const* d_in, const int* in_sizes, int n_in,
                              void* d_out, int out_size) {
    const float* future_fd = (const float*)d_in[0];
    const float* hidden    = (const float*)d_in[1];
    const float* cell      = (const float*)d_in[2];
    const float* W_ih      = (const float*)d_in[3];
    const float* W_hh      = (const float*)d_in[4];
    const float* b_ih      = (const float*)d_in[5];
    const float* b_hh      = (const float*)d_in[6];
    const float* fc_W      = (const float*)d_in[7];
    const float* fc_b      = (const float*)d_in[8];

    cudaFuncSetAttribute(step_kernel, cudaFuncAttributeMaxDynamicSharedMemorySize, SMEM_BYTES);

    prep_weights<<<(N4 * HH) / 256, 256>>>(W_hh, W_ih, b_ih, b_hh, fc_W);
    prep_state<<<(BATCH * HH) / 256, 256>>>(hidden, cell);
    for (int t = 0; t < TT; t++) {
        step_kernel<<<dim3(BATCH / TM, N4 / TN), NTHREADS, SMEM_BYTES>>>(t, future_fd, fc_b);
    }
    finalize_out<<<(BATCH * TT + 255) / 256, 256>>>((float*)d_out, fc_b);
}